// round 12
// baseline (speedup 1.0000x reference)
#include <cuda_runtime.h>
#include <cuda_fp16.h>
#include <math.h>
#include <stdint.h>

#define B    4
#define N    16384
#define CIN  4
#define SD   3
#define W    256
#define L    8
#define M    32
#define H    8
#define FF   1024
#define TF   4
#define DH   32
#define TOK1 32
#define TOKF 128
#define JC2  64

__device__ float g_x[(size_t)B * N * W];
__device__ float g_w[(size_t)B * N * M];
__device__ float g_z[(size_t)L * B * M * W];
__device__ float g_wsum[L * B * M];
__device__ float g_qkv[B * M * 3 * W];
__device__ float g_o[B * M * W];
__device__ float g_zp[B * M * W];
__device__ __align__(16) __half g_w1t[(size_t)L * FF * W];   // [L][FF][W] fp16
__device__ __align__(16) __half g_w2t[(size_t)L * W * FF];   // [L][W][FF] fp16

// ---------- helpers ----------
__device__ __forceinline__ int hw2(int r, int wc) { return r * 128 + (wc ^ ((r & 7) << 2)); }
__device__ __forceinline__ int gw2(int r, int wc) { return r * 32  + (wc ^ ((r & 7) << 2)); }
__device__ __forceinline__ void mma16(float* d, const uint32_t* a, const uint32_t* b) {
    asm volatile("mma.sync.aligned.m16n8k16.row.col.f32.f16.f16.f32 "
        "{%0,%1,%2,%3}, {%4,%5,%6,%7}, {%8,%9}, {%0,%1,%2,%3};"
        : "+f"(d[0]), "+f"(d[1]), "+f"(d[2]), "+f"(d[3])
        : "r"(a[0]), "r"(a[1]), "r"(a[2]), "r"(a[3]), "r"(b[0]), "r"(b[1]));
}
__device__ __forceinline__ void cp16(uint32_t* smem_dst, const void* gsrc) {
    uint32_t sa = (uint32_t)__cvta_generic_to_shared(smem_dst);
    asm volatile("cp.async.ca.shared.global [%0], [%1], 16;" :: "r"(sa), "l"(gsrc) : "memory");
}

// ---------------- K0: embed (16 tokens / block) ----------------
__global__ void __launch_bounds__(256) embed_kernel(
    const float* __restrict__ feat, const float* __restrict__ coords,
    const float* __restrict__ tn, const float* __restrict__ ew, const float* __restrict__ eb)
{
    __shared__ float f[16][16];
    int t0 = blockIdx.x * 16;
    int tid = threadIdx.x;
    {
        int t = tid >> 4, k = tid & 15;
        int token = t0 + t, b = token / N;
        float v = 0.f;
        if (k < CIN) v = feat[(size_t)token * CIN + k];
        else if (k < CIN + SD) v = coords[(size_t)token * SD + (k - CIN)];
        else if (k < 15) {
            int kk = k - 7, i = kk & 3;
            float ang = powf(1000.0f, -(float)i / (float)TF) * (tn[b] * 1000.0f);
            v = (kk < TF) ? sinf(ang) : cosf(ang);
        }
        f[t][k] = v;
    }
    __syncthreads();
    int c = tid;
    float wreg[15];
#pragma unroll
    for (int k = 0; k < 15; k++) wreg[k] = ew[k * W + c];
    float bias = eb[c];
#pragma unroll 4
    for (int t = 0; t < 16; t++) {
        float acc = bias;
#pragma unroll
        for (int k = 0; k < 15; k++) acc += f[t][k] * wreg[k];
        g_x[(size_t)(t0 + t) * W + c] = acc;
    }
}

// ---------------- weight transform + zero (fused) ----------------
__global__ void __launch_bounds__(256) w1t_kernel(const float* __restrict__ f1w)
{
    int idx = blockIdx.x * 256 + threadIdx.x;
    int l = idx / (FF * W), r = idx % (FF * W), j = r / W, c = r % W;
    g_w1t[((size_t)l * FF + j) * W + c] =
        __float2half(f1w[((size_t)l * W + c) * FF + j]);
}
#define NB_W2T (L * W * FF / 256)
#define NB_Z   (L * B * M * W / 256)
__global__ void __launch_bounds__(256) w2t_zero_kernel(const float* __restrict__ f2w)
{
    int bid = blockIdx.x;
    if (bid < NB_W2T) {
        int idx = bid * 256 + threadIdx.x;
        int l = idx / (W * FF), r = idx % (W * FF), c = r / FF, j = r % FF;
        g_w2t[((size_t)l * W + c) * FF + j] =
            __float2half(f2w[((size_t)l * FF + j) * W + c]);
    } else if (bid < NB_W2T + NB_Z) {
        int idx = (bid - NB_W2T) * 256 + threadIdx.x;
        g_z[idx] = 0.f;
    } else {
        for (int i = threadIdx.x; i < L * B * M; i += 256) g_wsum[i] = 0.f;
    }
}

// ---------------- K1: slice ----------------
__global__ void __launch_bounds__(256) slice_kernel(
    const float* __restrict__ ln_g, const float* __restrict__ ln_b,
    const float* __restrict__ sw, const float* __restrict__ sb, int layer)
{
    __shared__ float hs[TOK1][W];
    __shared__ float ws[TOK1][M];
    __shared__ float inv[TOK1];
    int nb = N / TOK1, b = blockIdx.x / nb, t0 = (blockIdx.x % nb) * TOK1;
    int tid = threadIdx.x, warp = tid >> 5, lane = tid & 31;
    const float* g = ln_g + layer * W;
    const float* be = ln_b + layer * W;
    float* zdst = g_z + (size_t)layer * B * M * W;
    float* wsdst = g_wsum + layer * B * M;

    for (int t = warp; t < TOK1; t += 8) {
        const float* xr = g_x + ((size_t)(b * N + t0 + t)) * W;
        float v[8]; float s = 0.f, s2 = 0.f;
#pragma unroll
        for (int i = 0; i < 8; i++) { v[i] = xr[lane + 32 * i]; s += v[i]; s2 += v[i] * v[i]; }
#pragma unroll
        for (int o = 16; o > 0; o >>= 1) {
            s += __shfl_xor_sync(0xffffffffu, s, o);
            s2 += __shfl_xor_sync(0xffffffffu, s2, o);
        }
        float mean = s * (1.0f / W), var = s2 * (1.0f / W) - mean * mean;
        float r = rsqrtf(var + 1e-5f);
#pragma unroll
        for (int i = 0; i < 8; i++) {
            int c = lane + 32 * i;
            hs[t][c] = (v[i] - mean) * r * g[c] + be[c];
        }
    }
    __syncthreads();

    // logits: thread -> (t, 4 m's); hs via LDS.128, weights via LDG.128
    const float* swl = sw + (size_t)layer * W * M;
    {
        int t = tid >> 3, m4 = (tid & 7) << 2;
        float4 acc = *(const float4*)&sb[layer * M + m4];
#pragma unroll 4
        for (int c4 = 0; c4 < W; c4 += 4) {
            float4 hv = *(const float4*)&hs[t][c4];
            float4 s0 = *(const float4*)&swl[(c4 + 0) * M + m4];
            float4 s1 = *(const float4*)&swl[(c4 + 1) * M + m4];
            float4 s2 = *(const float4*)&swl[(c4 + 2) * M + m4];
            float4 s3 = *(const float4*)&swl[(c4 + 3) * M + m4];
            acc.x += hv.x * s0.x + hv.y * s1.x + hv.z * s2.x + hv.w * s3.x;
            acc.y += hv.x * s0.y + hv.y * s1.y + hv.z * s2.y + hv.w * s3.y;
            acc.z += hv.x * s0.z + hv.y * s1.z + hv.z * s2.z + hv.w * s3.z;
            acc.w += hv.x * s0.w + hv.y * s1.w + hv.z * s2.w + hv.w * s3.w;
        }
        *(float4*)&ws[t][m4] = acc;
    }
    __syncthreads();

    if (tid < TOK1) {
        float mx = -1e30f;
#pragma unroll
        for (int m = 0; m < M; m++) mx = fmaxf(mx, ws[tid][m]);
        float sum = 0.f;
#pragma unroll
        for (int m = 0; m < M; m++) { float e = expf(ws[tid][m] - mx); ws[tid][m] = e; sum += e; }
        inv[tid] = 1.0f / sum;
    }
    __syncthreads();

    {
        int t = tid >> 3, m4 = (tid & 7) << 2;
        float iv = inv[t];
        float4 v = *(const float4*)&ws[t][m4];
        v.x *= iv; v.y *= iv; v.z *= iv; v.w *= iv;
        *(float4*)&ws[t][m4] = v;
        *(float4*)&g_w[((size_t)(b * N + t0 + t)) * M + m4] = v;
    }
    __syncthreads();

    if (tid < M) {
        float s = 0.f;
#pragma unroll
        for (int t = 0; t < TOK1; t++) s += ws[t][tid];
        atomicAdd(&wsdst[b * M + tid], s);
    }

    float zacc[M];
#pragma unroll
    for (int m = 0; m < M; m++) zacc[m] = 0.f;
    for (int t = 0; t < TOK1; t++) {
        float hv = hs[t][tid];
#pragma unroll
        for (int mq = 0; mq < 8; mq++) {
            float4 wv = *(const float4*)&ws[t][mq << 2];
            zacc[(mq << 2) + 0] += wv.x * hv;
            zacc[(mq << 2) + 1] += wv.y * hv;
            zacc[(mq << 2) + 2] += wv.z * hv;
            zacc[(mq << 2) + 3] += wv.w * hv;
        }
    }
#pragma unroll
    for (int m = 0; m < M; m++) atomicAdd(&zdst[(b * M + m) * W + tid], zacc[m]);
}

// ---------------- K2a: qkv (768 threads) ----------------
__global__ void __launch_bounds__(768) qkv_kernel(
    const float* __restrict__ qkvw, const float* __restrict__ qkvb, int layer)
{
    int b = blockIdx.x / M, m = blockIdx.x % M;
    __shared__ float zs[W];
    int tid = threadIdx.x;
    if (tid < W) {
        float wsv = fmaxf(g_wsum[layer * B * M + b * M + m], 1e-8f);
        zs[tid] = g_z[(size_t)layer * B * M * W + (size_t)(b * M + m) * W + tid] / wsv;
    }
    __syncthreads();
    const float* wq = qkvw + (size_t)layer * W * 3 * W;
    float acc = qkvb[layer * 3 * W + tid];
#pragma unroll 8
    for (int c = 0; c < W; c++) acc += zs[c] * wq[(size_t)c * (3 * W) + tid];
    g_qkv[(size_t)(b * M + m) * (3 * W) + tid] = acc;
}

__global__ void __launch_bounds__(256) attn_kernel()
{
    int b = blockIdx.x / H, h = blockIdx.x % H;
    __shared__ float q[M][DH], k[M][DH], v[M][DH], a[M][M];
    int tid = threadIdx.x;
    for (int i = tid; i < M * DH; i += 256) {
        int m = i / DH, d = i % DH;
        const float* base = g_qkv + (size_t)(b * M + m) * (3 * W);
        q[m][d] = base[h * DH + d];
        k[m][d] = base[W + h * DH + d];
        v[m][d] = base[2 * W + h * DH + d];
    }
    __syncthreads();
    const float scale = 0.17677669529663687f;
    for (int i = tid; i < M * M; i += 256) {
        int m = i / M, n2 = i % M;
        float acc = 0.f;
#pragma unroll
        for (int d = 0; d < DH; d++) acc += q[m][d] * k[n2][d];
        a[m][n2] = acc * scale;
    }
    __syncthreads();
    if (tid < M) {
        float mx = -1e30f;
#pragma unroll
        for (int n2 = 0; n2 < M; n2++) mx = fmaxf(mx, a[tid][n2]);
        float s = 0.f;
#pragma unroll
        for (int n2 = 0; n2 < M; n2++) { float e = expf(a[tid][n2] - mx); a[tid][n2] = e; s += e; }
        float is = 1.0f / s;
#pragma unroll
        for (int n2 = 0; n2 < M; n2++) a[tid][n2] *= is;
    }
    __syncthreads();
    for (int i = tid; i < M * DH; i += 256) {
        int m = i / DH, d = i % DH;
        float acc = 0.f;
#pragma unroll
        for (int n2 = 0; n2 < M; n2++) acc += a[m][n2] * v[n2][d];
        g_o[(size_t)(b * M + m) * W + h * DH + d] = acc;
    }
}
__global__ void __launch_bounds__(256) zp_kernel(
    const float* __restrict__ ow, const float* __restrict__ ob, int layer)
{
    int b = blockIdx.x / M, m = blockIdx.x % M;
    __shared__ float os[W];
    os[threadIdx.x] = g_o[(size_t)(b * M + m) * W + threadIdx.x];
    __syncthreads();
    const float* wl = ow + (size_t)layer * W * W;
    float acc = ob[layer * W + threadIdx.x];
#pragma unroll 8
    for (int k2 = 0; k2 < W; k2++) acc += os[k2] * wl[(size_t)k2 * W + threadIdx.x];
    g_zp[(size_t)(b * M + m) * W + threadIdx.x] = acc;
}

// ---------------- K3: FFN fp16 — cp.async double-buffered weights ----------
// word layout: h2[0,16384)  G[2]:16384..24576  B1[2]:24576..40960  B2[2]:40960..57344
#define WO_G   16384
#define WO_B1  24576
#define WO_B2  40960
#define SM_FFN_BYTES (57344 * 4)      // 229376

__global__ void __launch_bounds__(512, 1) ffn_mma_kernel(
    const float* __restrict__ ln2g, const float* __restrict__ ln2b,
    const float* __restrict__ f1b, const float* __restrict__ f2b, int layer)
{
    extern __shared__ uint32_t usm[];
    uint32_t* u_h2 = usm;
    __half* h_h2 = (__half*)u_h2;
    int tid = threadIdx.x;
    int warp = tid >> 5, lane = tid & 31, g = lane >> 2, tig = lane & 3;
    int nb = N / TOKF, b = blockIdx.x / nb, t0 = (blockIdx.x % nb) * TOKF;
    size_t xbase = ((size_t)(b * N) + t0) * W;

    const __half* w1l = g_w1t + (size_t)layer * FF * W;
    const __half* w2l = g_w2t + (size_t)layer * W * FF;

    // ---- prologue: x_mid = x + w@zp ----
    int c = tid & 255, half_ = tid >> 8;
    float zpc[M];
#pragma unroll
    for (int m = 0; m < M; m++) zpc[m] = g_zp[(size_t)(b * M + m) * W + c];
    {
        float* s_w = (float*)(usm + WO_G);
        for (int i = tid; i < TOKF * M; i += 512)
            s_w[i] = g_w[((size_t)(b * N) + t0 + i / M) * M + (i % M)];
        __syncthreads();
        int wcol = c >> 1, hi = c & 1;
        for (int t = half_ * 64; t < half_ * 64 + 64; t++) {
            float acc = g_x[xbase + (size_t)t * W + c];
#pragma unroll
            for (int m = 0; m < M; m++) acc += s_w[t * M + m] * zpc[m];
            g_x[xbase + (size_t)t * W + c] = acc;
            h_h2[(t * 128 + (wcol ^ ((t & 7) << 2))) * 2 + hi] = __float2half(acc);
        }
    }
    __syncthreads();

    // ---- LN2 in place on fp16 h2 ----
    {
        const float* g2 = ln2g + layer * W;
        const float* b2 = ln2b + layer * W;
        for (int rr = 0; rr < 8; rr++) {
            int r = warp * 8 + rr;
            if (r >= TOKF) break;
            float v[8]; float s = 0.f, s2 = 0.f;
#pragma unroll
            for (int i = 0; i < 8; i++) {
                int ci = lane + 32 * i;
                v[i] = __half2float(h_h2[(r * 128 + ((ci >> 1) ^ ((r & 7) << 2))) * 2 + (ci & 1)]);
                s += v[i]; s2 += v[i] * v[i];
            }
#pragma unroll
            for (int o = 16; o > 0; o >>= 1) {
                s += __shfl_xor_sync(0xffffffffu, s, o);
                s2 += __shfl_xor_sync(0xffffffffu, s2, o);
            }
            float mean = s * (1.0f / W), var = s2 * (1.0f / W) - mean * mean;
            float rs = rsqrtf(var + 1e-5f);
#pragma unroll
            for (int i = 0; i < 8; i++) {
                int ci = lane + 32 * i;
                h_h2[(r * 128 + ((ci >> 1) ^ ((r & 7) << 2))) * 2 + (ci & 1)] =
                    __float2half((v[i] - mean) * rs * g2[ci] + b2[ci]);
            }
        }
    }

    const float* b1l = f1b + layer * FF;
    int wm = warp >> 2, wn = warp & 3;
    float d2[2][8][4];
#pragma unroll
    for (int mt = 0; mt < 2; mt++)
#pragma unroll
        for (int nt = 0; nt < 8; nt++)
#pragma unroll
            for (int q = 0; q < 4; q++) d2[mt][nt][q] = 0.f;

    // ---- prefetch chunk 0 weight slices into parity 0 ----
    {
        uint32_t* b1d = usm + WO_B1;
        uint32_t* b2d = usm + WO_B2;
#pragma unroll
        for (int it = 0; it < 4; it++) {
            int idx = it * 512 + tid;
            int jl = idx >> 5, wc4 = (idx & 31) << 2;
            cp16(&b1d[jl * 128 + (wc4 ^ ((jl & 7) << 2))], w1l + (size_t)jl * W + wc4 * 2);
        }
#pragma unroll
        for (int it = 0; it < 4; it++) {
            int idx = it * 512 + tid;
            int cc = idx >> 3, wc4 = (idx & 7) << 2;
            cp16(&b2d[cc * 32 + (wc4 ^ ((cc & 7) << 2))], w2l + (size_t)cc * FF + wc4 * 2);
        }
        asm volatile("cp.async.commit_group;" ::: "memory");
    }

    for (int chunk = 0; chunk < 16; chunk++) {
        int par = chunk & 1;
        int j0 = chunk * JC2;
        uint32_t* u_b1 = usm + WO_B1 + par * 8192;
        uint32_t* u_b2 = usm + WO_B2 + par * 8192;
        uint32_t* u_g  = usm + WO_G  + par * 4096;

        asm volatile("cp.async.wait_group 0;" ::: "memory");
        __syncthreads();

        // prefetch next chunk into opposite parity
        if (chunk + 1 < 16) {
            int j1 = j0 + JC2;
            uint32_t* n_b1 = usm + WO_B1 + (par ^ 1) * 8192;
            uint32_t* n_b2 = usm + WO_B2 + (par ^ 1) * 8192;
#pragma unroll
            for (int it = 0; it < 4; it++) {
                int idx = it * 512 + tid;
                int jl = idx >> 5, wc4 = (idx & 31) << 2;
                cp16(&n_b1[jl * 128 + (wc4 ^ ((jl & 7) << 2))], w1l + (size_t)(j1 + jl) * W + wc4 * 2);
            }
#pragma unroll
            for (int it = 0; it < 4; it++) {
                int idx = it * 512 + tid;
                int cc = idx >> 3, wc4 = (idx & 7) << 2;
                cp16(&n_b2[cc * 32 + (wc4 ^ ((cc & 7) << 2))], w2l + (size_t)cc * FF + j1 + wc4 * 2);
            }
            asm volatile("cp.async.commit_group;" ::: "memory");
        }

        // ===== GEMM1: D1[128x64] = h2 @ B1, K=256 =====
        float d1[2][2][4];
#pragma unroll
        for (int mt = 0; mt < 2; mt++)
#pragma unroll
            for (int nt = 0; nt < 2; nt++)
#pragma unroll
                for (int q = 0; q < 4; q++) d1[mt][nt][q] = 0.f;

#pragma unroll 4
        for (int ks = 0; ks < 16; ks++) {
            int kwb = ks * 8;
            uint32_t af[2][4];
#pragma unroll
            for (int mt = 0; mt < 2; mt++) {
                int r0 = wm * 32 + mt * 16 + g;
                af[mt][0] = u_h2[hw2(r0,     kwb + tig)];
                af[mt][1] = u_h2[hw2(r0 + 8, kwb + tig)];
                af[mt][2] = u_h2[hw2(r0,     kwb + tig + 4)];
                af[mt][3] = u_h2[hw2(r0 + 8, kwb + tig + 4)];
            }
#pragma unroll
            for (int nt = 0; nt < 2; nt++) {
                int jl = wn * 16 + nt * 8 + g;
                uint32_t bf[2];
                bf[0] = u_b1[hw2(jl, kwb + tig)];
                bf[1] = u_b1[hw2(jl, kwb + tig + 4)];
                mma16(d1[0][nt], af[0], bf);
                mma16(d1[1][nt], af[1], bf);
            }
        }

        asm volatile("bar.sync %0, 128;" :: "r"(wm + 1) : "memory");

        // ---- gelu -> G[par] (wm-group-private rows) ----
#pragma unroll
        for (int mt = 0; mt < 2; mt++) {
#pragma unroll
            for (int nt = 0; nt < 2; nt++) {
                int r0 = wm * 32 + mt * 16 + g;
                int jc = wn * 16 + nt * 8 + 2 * tig;
                int wc = wn * 8 + nt * 4 + tig;
                float x0 = d1[mt][nt][0] + b1l[j0 + jc];
                float x1 = d1[mt][nt][1] + b1l[j0 + jc + 1];
                float x2 = d1[mt][nt][2] + b1l[j0 + jc];
                float x3 = d1[mt][nt][3] + b1l[j0 + jc + 1];
                float g0 = 0.5f * x0 * (1.0f + erff(x0 * 0.7071067811865476f));
                float g1 = 0.5f * x1 * (1.0f + erff(x1 * 0.7071067811865476f));
                float g2v = 0.5f * x2 * (1.0f + erff(x2 * 0.7071067811865476f));
                float g3 = 0.5f * x3 * (1.0f + erff(x3 * 0.7071067811865476f));
                __half2 p0 = __floats2half2_rn(g0, g1);
                __half2 p1 = __floats2half2_rn(g2v, g3);
                u_g[gw2(r0,     wc)] = *(uint32_t*)&p0;
                u_g[gw2(r0 + 8, wc)] = *(uint32_t*)&p1;
            }
        }

        asm volatile("bar.sync %0, 128;" :: "r"(wm + 1) : "memory");

        // ===== GEMM2 partial: D2 += G @ B2, K=64 =====
#pragma unroll
        for (int ks = 0; ks < 4; ks++) {
            int kwb = ks * 8;
            uint32_t af[2][4];
#pragma unroll
            for (int mt = 0; mt < 2; mt++) {
                int r0 = wm * 32 + mt * 16 + g;
                af[mt][0] = u_g[gw2(r0,     kwb + tig)];
                af[mt][1] = u_g[gw2(r0 + 8, kwb + tig)];
                af[mt][2] = u_g[gw2(r0,     kwb + tig + 4)];
                af[mt][3] = u_g[gw2(r0 + 8, kwb + tig + 4)];
            }
#pragma unroll
            for (int nt = 0; nt < 8; nt++) {
                int cc = wn * 64 + nt * 8 + g;
                uint32_t bf[2];
                bf[0] = u_b2[gw2(cc, kwb + tig)];
                bf[1] = u_b2[gw2(cc, kwb + tig + 4)];
                mma16(d2[0][nt], af[0], bf);
                mma16(d2[1][nt], af[1], bf);
            }
        }
    }

    // ---- epilogue: x = x_mid + D2 + b2 ----
    const float* b2l = f2b + layer * W;
#pragma unroll
    for (int mt = 0; mt < 2; mt++) {
#pragma unroll
        for (int nt = 0; nt < 8; nt++) {
            int col = wn * 64 + nt * 8 + 2 * tig;
            int ra = wm * 32 + mt * 16 + g;
            float2 xm = *(const float2*)&g_x[xbase + (size_t)ra * W + col];
            float2 o;
            o.x = xm.x + d2[mt][nt][0] + b2l[col];
            o.y = xm.y + d2[mt][nt][1] + b2l[col + 1];
            *(float2*)&g_x[xbase + (size_t)ra * W + col] = o;
            int rb = ra + 8;
            float2 xm2 = *(const float2*)&g_x[xbase + (size_t)rb * W + col];
            o.x = xm2.x + d2[mt][nt][2] + b2l[col];
            o.y = xm2.y + d2[mt][nt][3] + b2l[col + 1];
            *(float2*)&g_x[xbase + (size_t)rb * W + col] = o;
        }
    }
}

// ---------------- K5: final projection ----------------
__global__ void __launch_bounds__(256) proj_kernel(
    const float* __restrict__ pw, const float* __restrict__ pb, float* __restrict__ out)
{
    __shared__ float xs[16][W];
    size_t t0 = (size_t)blockIdx.x * 16;
    for (int i = threadIdx.x; i < 16 * W; i += 256)
        xs[i >> 8][i & 255] = g_x[t0 * W + i];
    __syncthreads();
    if (threadIdx.x < 64) {
        int t = threadIdx.x >> 2, o = threadIdx.x & 3;
        float acc = pb[o];
#pragma unroll 8
        for (int c = 0; c < W; c++) acc += xs[t][c] * pw[c * CIN + o];
        out[(t0 + t) * CIN + o] = acc;
    }
}

// ---------------- launch ----------------
extern "C" void kernel_launch(void* const* d_in, const int* in_sizes, int n_in,
                              void* d_out, int out_size)
{
    const float* feat = (const float*)d_in[0];
    const float* coords = (const float*)d_in[1];
    const float* tn   = (const float*)d_in[2];
    const float* ew   = (const float*)d_in[3];
    const float* eb   = (const float*)d_in[4];
    const float* ln1g = (const float*)d_in[5];
    const float* ln1b = (const float*)d_in[6];
    const float* sw   = (const float*)d_in[7];
    const float* sb   = (const float*)d_in[8];
    const float* qkvw = (const float*)d_in[9];
    const float* qkvb = (const float*)d_in[10];
    const float* outw = (const float*)d_in[11];
    const float* outb = (const float*)d_in[12];
    const float* ln2g = (const float*)d_in[13];
    const float* ln2b = (const float*)d_in[14];
    const float* f1w  = (const float*)d_in[15];
    const float* f1b  = (const float*)d_in[16];
    const float* f2w  = (const float*)d_in[17];
    const float* f2b  = (const float*)d_in[18];
    const float* pw   = (const float*)d_in[19];
    const float* pb   = (const float*)d_in[20];

    static int attr_set = 0;
    if (!attr_set) {
        cudaFuncSetAttribute(ffn_mma_kernel, cudaFuncAttributeMaxDynamicSharedMemorySize, SM_FFN_BYTES);
        attr_set = 1;
    }

    embed_kernel<<<B * N / 16, 256>>>(feat, coords, tn, ew, eb);
    w1t_kernel<<<L * FF * W / 256, 256>>>(f1w);
    w2t_zero_kernel<<<NB_W2T + NB_Z + 1, 256>>>(f2w);

    for (int l = 0; l < L; l++) {
        slice_kernel<<<B * (N / TOK1), 256>>>(ln1g, ln1b, sw, sb, l);
        qkv_kernel<<<B * M, 768>>>(qkvw, qkvb, l);
        attn_kernel<<<B * H, 256>>>();
        zp_kernel<<<B * M, 256>>>(outw, outb, l);
        ffn_mma_kernel<<<B * (N / TOKF), 512, SM_FFN_BYTES>>>(ln2g, ln2b, f1b, f2b, l);
    }

    proj_kernel<<<(B * N) / 16, 256>>>(pw, pb, (float*)d_out);
}

// round 13
// speedup vs baseline: 1.0814x; 1.0814x over previous
#include <cuda_runtime.h>
#include <cuda_fp16.h>
#include <math.h>
#include <stdint.h>

#define B    4
#define N    16384
#define CIN  4
#define SD   3
#define W    256
#define L    8
#define M    32
#define H    8
#define FF   1024
#define TF   4
#define DH   32
#define TOK1 32
#define TOKF 128
#define JC2  128

__device__ float g_x[(size_t)B * N * W];
__device__ float g_w[(size_t)B * N * M];
__device__ float g_z[(size_t)L * B * M * W];
__device__ float g_wsum[L * B * M];
__device__ float g_qkv[B * M * 3 * W];
__device__ float g_o[B * M * W];
__device__ float g_zp[B * M * W];
__device__ __align__(16) __half g_w1t[(size_t)L * FF * W];   // [L][FF][W] fp16
__device__ __align__(16) __half g_w2t[(size_t)L * W * FF];   // [L][W][FF] fp16

// ---------- helpers ----------
__device__ __forceinline__ int hw2(int r, int wc) { return r * 128 + (wc ^ ((r & 7) << 2)); }  // 128 w/row
__device__ __forceinline__ int g2w(int r, int wc) { return r * 64  + (wc ^ ((r & 7) << 2)); }  // 64 w/row
__device__ __forceinline__ void mma16(float* d, const uint32_t* a, const uint32_t* b) {
    asm volatile("mma.sync.aligned.m16n8k16.row.col.f32.f16.f16.f32 "
        "{%0,%1,%2,%3}, {%4,%5,%6,%7}, {%8,%9}, {%0,%1,%2,%3};"
        : "+f"(d[0]), "+f"(d[1]), "+f"(d[2]), "+f"(d[3])
        : "r"(a[0]), "r"(a[1]), "r"(a[2]), "r"(a[3]), "r"(b[0]), "r"(b[1]));
}

// ---------------- K0: embed (16 tokens / block) ----------------
__global__ void __launch_bounds__(256) embed_kernel(
    const float* __restrict__ feat, const float* __restrict__ coords,
    const float* __restrict__ tn, const float* __restrict__ ew, const float* __restrict__ eb)
{
    __shared__ float f[16][16];
    int t0 = blockIdx.x * 16;
    int tid = threadIdx.x;
    {
        int t = tid >> 4, k = tid & 15;
        int token = t0 + t, b = token / N;
        float v = 0.f;
        if (k < CIN) v = feat[(size_t)token * CIN + k];
        else if (k < CIN + SD) v = coords[(size_t)token * SD + (k - CIN)];
        else if (k < 15) {
            int kk = k - 7, i = kk & 3;
            float ang = powf(1000.0f, -(float)i / (float)TF) * (tn[b] * 1000.0f);
            v = (kk < TF) ? sinf(ang) : cosf(ang);
        }
        f[t][k] = v;
    }
    __syncthreads();
    int c = tid;
    float wreg[15];
#pragma unroll
    for (int k = 0; k < 15; k++) wreg[k] = ew[k * W + c];
    float bias = eb[c];
#pragma unroll 4
    for (int t = 0; t < 16; t++) {
        float acc = bias;
#pragma unroll
        for (int k = 0; k < 15; k++) acc += f[t][k] * wreg[k];
        g_x[(size_t)(t0 + t) * W + c] = acc;
    }
}

// ---------------- weight transform + zero (fused) ----------------
__global__ void __launch_bounds__(256) w1t_kernel(const float* __restrict__ f1w)
{
    int idx = blockIdx.x * 256 + threadIdx.x;
    int l = idx / (FF * W), r = idx % (FF * W), j = r / W, c = r % W;
    g_w1t[((size_t)l * FF + j) * W + c] =
        __float2half(f1w[((size_t)l * W + c) * FF + j]);
}
#define NB_W2T (L * W * FF / 256)
#define NB_Z   (L * B * M * W / 256)
__global__ void __launch_bounds__(256) w2t_zero_kernel(const float* __restrict__ f2w)
{
    int bid = blockIdx.x;
    if (bid < NB_W2T) {
        int idx = bid * 256 + threadIdx.x;
        int l = idx / (W * FF), r = idx % (W * FF), c = r / FF, j = r % FF;
        g_w2t[((size_t)l * W + c) * FF + j] =
            __float2half(f2w[((size_t)l * FF + j) * W + c]);
    } else if (bid < NB_W2T + NB_Z) {
        int idx = (bid - NB_W2T) * 256 + threadIdx.x;
        g_z[idx] = 0.f;
    } else {
        for (int i = threadIdx.x; i < L * B * M; i += 256) g_wsum[i] = 0.f;
    }
}

// ---------------- K1: slice ----------------
__global__ void __launch_bounds__(256, 4) slice_kernel(
    const float* __restrict__ ln_g, const float* __restrict__ ln_b,
    const float* __restrict__ sw, const float* __restrict__ sb, int layer)
{
    __shared__ float hs[TOK1][W];
    __shared__ float ws[TOK1][M];
    __shared__ float inv[TOK1];
    int nb = N / TOK1, b = blockIdx.x / nb, t0 = (blockIdx.x % nb) * TOK1;
    int tid = threadIdx.x, warp = tid >> 5, lane = tid & 31;
    const float* g = ln_g + layer * W;
    const float* be = ln_b + layer * W;
    float* zdst = g_z + (size_t)layer * B * M * W;
    float* wsdst = g_wsum + layer * B * M;

    for (int t = warp; t < TOK1; t += 8) {
        const float* xr = g_x + ((size_t)(b * N + t0 + t)) * W;
        float v[8]; float s = 0.f, s2 = 0.f;
#pragma unroll
        for (int i = 0; i < 8; i++) { v[i] = xr[lane + 32 * i]; s += v[i]; s2 += v[i] * v[i]; }
#pragma unroll
        for (int o = 16; o > 0; o >>= 1) {
            s += __shfl_xor_sync(0xffffffffu, s, o);
            s2 += __shfl_xor_sync(0xffffffffu, s2, o);
        }
        float mean = s * (1.0f / W), var = s2 * (1.0f / W) - mean * mean;
        float r = rsqrtf(var + 1e-5f);
#pragma unroll
        for (int i = 0; i < 8; i++) {
            int c = lane + 32 * i;
            hs[t][c] = (v[i] - mean) * r * g[c] + be[c];
        }
    }
    __syncthreads();

    // logits: thread -> (t, 4 m's); hs via LDS.128, weights via LDG.128
    const float* swl = sw + (size_t)layer * W * M;
    {
        int t = tid >> 3, m4 = (tid & 7) << 2;
        float4 acc = *(const float4*)&sb[layer * M + m4];
#pragma unroll 4
        for (int c4 = 0; c4 < W; c4 += 4) {
            float4 hv = *(const float4*)&hs[t][c4];
            float4 s0 = *(const float4*)&swl[(c4 + 0) * M + m4];
            float4 s1 = *(const float4*)&swl[(c4 + 1) * M + m4];
            float4 s2 = *(const float4*)&swl[(c4 + 2) * M + m4];
            float4 s3 = *(const float4*)&swl[(c4 + 3) * M + m4];
            acc.x += hv.x * s0.x + hv.y * s1.x + hv.z * s2.x + hv.w * s3.x;
            acc.y += hv.x * s0.y + hv.y * s1.y + hv.z * s2.y + hv.w * s3.y;
            acc.z += hv.x * s0.z + hv.y * s1.z + hv.z * s2.z + hv.w * s3.z;
            acc.w += hv.x * s0.w + hv.y * s1.w + hv.z * s2.w + hv.w * s3.w;
        }
        *(float4*)&ws[t][m4] = acc;
    }
    __syncthreads();

    if (tid < TOK1) {
        float mx = -1e30f;
#pragma unroll
        for (int m = 0; m < M; m++) mx = fmaxf(mx, ws[tid][m]);
        float sum = 0.f;
#pragma unroll
        for (int m = 0; m < M; m++) { float e = expf(ws[tid][m] - mx); ws[tid][m] = e; sum += e; }
        inv[tid] = 1.0f / sum;
    }
    __syncthreads();

    {
        int t = tid >> 3, m4 = (tid & 7) << 2;
        float iv = inv[t];
        float4 v = *(const float4*)&ws[t][m4];
        v.x *= iv; v.y *= iv; v.z *= iv; v.w *= iv;
        *(float4*)&ws[t][m4] = v;
        *(float4*)&g_w[((size_t)(b * N + t0 + t)) * M + m4] = v;
    }
    __syncthreads();

    if (tid < M) {
        float s = 0.f;
#pragma unroll
        for (int t = 0; t < TOK1; t++) s += ws[t][tid];
        atomicAdd(&wsdst[b * M + tid], s);
    }

    float zacc[M];
#pragma unroll
    for (int m = 0; m < M; m++) zacc[m] = 0.f;
    for (int t = 0; t < TOK1; t++) {
        float hv = hs[t][tid];
#pragma unroll
        for (int mq = 0; mq < 8; mq++) {
            float4 wv = *(const float4*)&ws[t][mq << 2];
            zacc[(mq << 2) + 0] += wv.x * hv;
            zacc[(mq << 2) + 1] += wv.y * hv;
            zacc[(mq << 2) + 2] += wv.z * hv;
            zacc[(mq << 2) + 3] += wv.w * hv;
        }
    }
#pragma unroll
    for (int m = 0; m < M; m++) atomicAdd(&zdst[(b * M + m) * W + tid], zacc[m]);
}

// ---------------- K2a: qkv (768 threads) ----------------
__global__ void __launch_bounds__(768) qkv_kernel(
    const float* __restrict__ qkvw, const float* __restrict__ qkvb, int layer)
{
    int b = blockIdx.x / M, m = blockIdx.x % M;
    __shared__ float zs[W];
    int tid = threadIdx.x;
    if (tid < W) {
        float wsv = fmaxf(g_wsum[layer * B * M + b * M + m], 1e-8f);
        zs[tid] = g_z[(size_t)layer * B * M * W + (size_t)(b * M + m) * W + tid] / wsv;
    }
    __syncthreads();
    const float* wq = qkvw + (size_t)layer * W * 3 * W;
    float acc = qkvb[layer * 3 * W + tid];
#pragma unroll 8
    for (int c = 0; c < W; c++) acc += zs[c] * wq[(size_t)c * (3 * W) + tid];
    g_qkv[(size_t)(b * M + m) * (3 * W) + tid] = acc;
}

__global__ void __launch_bounds__(256) attn_kernel()
{
    int b = blockIdx.x / H, h = blockIdx.x % H;
    __shared__ float q[M][DH], k[M][DH], v[M][DH], a[M][M];
    int tid = threadIdx.x;
    for (int i = tid; i < M * DH; i += 256) {
        int m = i / DH, d = i % DH;
        const float* base = g_qkv + (size_t)(b * M + m) * (3 * W);
        q[m][d] = base[h * DH + d];
        k[m][d] = base[W + h * DH + d];
        v[m][d] = base[2 * W + h * DH + d];
    }
    __syncthreads();
    const float scale = 0.17677669529663687f;
    for (int i = tid; i < M * M; i += 256) {
        int m = i / M, n2 = i % M;
        float acc = 0.f;
#pragma unroll
        for (int d = 0; d < DH; d++) acc += q[m][d] * k[n2][d];
        a[m][n2] = acc * scale;
    }
    __syncthreads();
    if (tid < M) {
        float mx = -1e30f;
#pragma unroll
        for (int n2 = 0; n2 < M; n2++) mx = fmaxf(mx, a[tid][n2]);
        float s = 0.f;
#pragma unroll
        for (int n2 = 0; n2 < M; n2++) { float e = expf(a[tid][n2] - mx); a[tid][n2] = e; s += e; }
        float is = 1.0f / s;
#pragma unroll
        for (int n2 = 0; n2 < M; n2++) a[tid][n2] *= is;
    }
    __syncthreads();
    for (int i = tid; i < M * DH; i += 256) {
        int m = i / DH, d = i % DH;
        float acc = 0.f;
#pragma unroll
        for (int n2 = 0; n2 < M; n2++) acc += a[m][n2] * v[n2][d];
        g_o[(size_t)(b * M + m) * W + h * DH + d] = acc;
    }
}
__global__ void __launch_bounds__(256) zp_kernel(
    const float* __restrict__ ow, const float* __restrict__ ob, int layer)
{
    int b = blockIdx.x / M, m = blockIdx.x % M;
    __shared__ float os[W];
    os[threadIdx.x] = g_o[(size_t)(b * M + m) * W + threadIdx.x];
    __syncthreads();
    const float* wl = ow + (size_t)layer * W * W;
    float acc = ob[layer * W + threadIdx.x];
#pragma unroll 8
    for (int k2 = 0; k2 < W; k2++) acc += os[k2] * wl[(size_t)k2 * W + threadIdx.x];
    g_zp[(size_t)(b * M + m) * W + threadIdx.x] = acc;
}

// ---------------- K3: FFN fp16 m16n8k16, JC2=128 (8 chunks) ----------------
// words: h2[0,16384)  G[16384,24576)  B[24576,40960)   == 160 KB
#define WO_G 16384
#define WO_B 24576
#define SM_FFN_BYTES (40960 * 4)

__global__ void __launch_bounds__(512, 1) ffn_mma_kernel(
    const float* __restrict__ ln2g, const float* __restrict__ ln2b,
    const float* __restrict__ f1b, const float* __restrict__ f2b, int layer)
{
    extern __shared__ uint32_t usm[];
    uint32_t* u_h2 = usm;
    uint32_t* u_g  = usm + WO_G;
    uint32_t* u_b  = usm + WO_B;
    __half* h_h2 = (__half*)u_h2;
    int tid = threadIdx.x;
    int warp = tid >> 5, lane = tid & 31, g = lane >> 2, tig = lane & 3;
    int nb = N / TOKF, b = blockIdx.x / nb, t0 = (blockIdx.x % nb) * TOKF;
    size_t xbase = ((size_t)(b * N) + t0) * W;

    // ---- prologue: x_mid = x + w@zp ----
    int c = tid & 255, half_ = tid >> 8;
    float zpc[M];
#pragma unroll
    for (int m = 0; m < M; m++) zpc[m] = g_zp[(size_t)(b * M + m) * W + c];
    {
        float* s_w = (float*)u_g;
        for (int i = tid; i < TOKF * M; i += 512)
            s_w[i] = g_w[((size_t)(b * N) + t0 + i / M) * M + (i % M)];
        __syncthreads();
        int wcol = c >> 1, hi = c & 1;
        for (int t = half_ * 64; t < half_ * 64 + 64; t++) {
            float acc = g_x[xbase + (size_t)t * W + c];
#pragma unroll
            for (int m = 0; m < M; m++) acc += s_w[t * M + m] * zpc[m];
            g_x[xbase + (size_t)t * W + c] = acc;
            h_h2[(t * 128 + (wcol ^ ((t & 7) << 2))) * 2 + hi] = __float2half(acc);
        }
    }
    __syncthreads();

    // ---- LN2 in place on fp16 h2 ----
    {
        const float* g2 = ln2g + layer * W;
        const float* b2 = ln2b + layer * W;
        for (int rr = 0; rr < 8; rr++) {
            int r = warp * 8 + rr;
            if (r >= TOKF) break;
            float v[8]; float s = 0.f, s2 = 0.f;
#pragma unroll
            for (int i = 0; i < 8; i++) {
                int ci = lane + 32 * i;
                v[i] = __half2float(h_h2[(r * 128 + ((ci >> 1) ^ ((r & 7) << 2))) * 2 + (ci & 1)]);
                s += v[i]; s2 += v[i] * v[i];
            }
#pragma unroll
            for (int o = 16; o > 0; o >>= 1) {
                s += __shfl_xor_sync(0xffffffffu, s, o);
                s2 += __shfl_xor_sync(0xffffffffu, s2, o);
            }
            float mean = s * (1.0f / W), var = s2 * (1.0f / W) - mean * mean;
            float rs = rsqrtf(var + 1e-5f);
#pragma unroll
            for (int i = 0; i < 8; i++) {
                int ci = lane + 32 * i;
                h_h2[(r * 128 + ((ci >> 1) ^ ((r & 7) << 2))) * 2 + (ci & 1)] =
                    __float2half((v[i] - mean) * rs * g2[ci] + b2[ci]);
            }
        }
    }

    const __half* w1l = g_w1t + (size_t)layer * FF * W;
    const __half* w2l = g_w2t + (size_t)layer * W * FF;
    const float* b1l = f1b + layer * FF;

    int wm = warp >> 2, wn = warp & 3;
    float d2[2][8][4];
#pragma unroll
    for (int mt = 0; mt < 2; mt++)
#pragma unroll
        for (int nt = 0; nt < 8; nt++)
#pragma unroll
            for (int q = 0; q < 4; q++) d2[mt][nt][q] = 0.f;

    for (int chunk = 0; chunk < 8; chunk++) {
        int j0 = chunk * JC2;

        __syncthreads();   // prior GEMM2 done reading u_b; prologue/LN done (chunk 0)
        // ---- stage B1 = W1T[j0..j0+128)[0..256) fp16, 64KB ----
#pragma unroll
        for (int it = 0; it < 8; it++) {
            int idx = it * 512 + tid;               // 4096 uint4
            int jl = idx >> 5, wc4 = (idx & 31) << 2;
            uint4 v = *(const uint4*)&w1l[(size_t)(j0 + jl) * W + wc4 * 2];
            *(uint4*)&u_b[jl * 128 + (wc4 ^ ((jl & 7) << 2))] = v;
        }
        __syncthreads();

        // ===== GEMM1: D1[128x128] = h2 @ B1, K=256 (16 k-steps) =====
        float d1[2][4][4];
#pragma unroll
        for (int mt = 0; mt < 2; mt++)
#pragma unroll
            for (int nt = 0; nt < 4; nt++)
#pragma unroll
                for (int q = 0; q < 4; q++) d1[mt][nt][q] = 0.f;

#pragma unroll 4
        for (int ks = 0; ks < 16; ks++) {
            int kwb = ks * 8;
            uint32_t af[2][4];
#pragma unroll
            for (int mt = 0; mt < 2; mt++) {
                int r0 = wm * 32 + mt * 16 + g;
                af[mt][0] = u_h2[hw2(r0,     kwb + tig)];
                af[mt][1] = u_h2[hw2(r0 + 8, kwb + tig)];
                af[mt][2] = u_h2[hw2(r0,     kwb + tig + 4)];
                af[mt][3] = u_h2[hw2(r0 + 8, kwb + tig + 4)];
            }
#pragma unroll
            for (int nt = 0; nt < 4; nt++) {
                int jl = wn * 32 + nt * 8 + g;
                uint32_t bf[2];
                bf[0] = u_b[hw2(jl, kwb + tig)];
                bf[1] = u_b[hw2(jl, kwb + tig + 4)];
                mma16(d1[0][nt], af[0], bf);
                mma16(d1[1][nt], af[1], bf);
            }
        }
        __syncthreads();   // GEMM1 reads of u_b done; prior GEMM2 reads of u_g done

        // ---- gelu -> G (fp16, 128x128) ; stage B2 = W2T[0..256)[j0..j0+128) ----
#pragma unroll
        for (int mt = 0; mt < 2; mt++) {
#pragma unroll
            for (int nt = 0; nt < 4; nt++) {
                int r0 = wm * 32 + mt * 16 + g;
                int jc = wn * 32 + nt * 8 + 2 * tig;
                int wc = wn * 16 + nt * 4 + tig;
                float x0 = d1[mt][nt][0] + b1l[j0 + jc];
                float x1 = d1[mt][nt][1] + b1l[j0 + jc + 1];
                float x2 = d1[mt][nt][2] + b1l[j0 + jc];
                float x3 = d1[mt][nt][3] + b1l[j0 + jc + 1];
                float g0 = 0.5f * x0 * (1.0f + erff(x0 * 0.7071067811865476f));
                float g1 = 0.5f * x1 * (1.0f + erff(x1 * 0.7071067811865476f));
                float g2v = 0.5f * x2 * (1.0f + erff(x2 * 0.7071067811865476f));
                float g3 = 0.5f * x3 * (1.0f + erff(x3 * 0.7071067811865476f));
                __half2 p0 = __floats2half2_rn(g0, g1);
                __half2 p1 = __floats2half2_rn(g2v, g3);
                u_g[g2w(r0,     wc)] = *(uint32_t*)&p0;
                u_g[g2w(r0 + 8, wc)] = *(uint32_t*)&p1;
            }
        }
#pragma unroll
        for (int it = 0; it < 8; it++) {
            int idx = it * 512 + tid;               // 4096 uint4
            int cc = idx >> 4, wc4 = (idx & 15) << 2;
            uint4 v = *(const uint4*)&w2l[(size_t)cc * FF + j0 + wc4 * 2];
            *(uint4*)&u_b[cc * 64 + (wc4 ^ ((cc & 7) << 2))] = v;
        }
        __syncthreads();

        // ===== GEMM2 partial: D2[128x256] += G @ B2, K=128 (8 k-steps) =====
#pragma unroll 2
        for (int ks = 0; ks < 8; ks++) {
            int kwb = ks * 8;
            uint32_t af[2][4];
#pragma unroll
            for (int mt = 0; mt < 2; mt++) {
                int r0 = wm * 32 + mt * 16 + g;
                af[mt][0] = u_g[g2w(r0,     kwb + tig)];
                af[mt][1] = u_g[g2w(r0 + 8, kwb + tig)];
                af[mt][2] = u_g[g2w(r0,     kwb + tig + 4)];
                af[mt][3] = u_g[g2w(r0 + 8, kwb + tig + 4)];
            }
#pragma unroll
            for (int nt = 0; nt < 8; nt++) {
                int cc = wn * 64 + nt * 8 + g;
                uint32_t bf[2];
                bf[0] = u_b[g2w(cc, kwb + tig)];
                bf[1] = u_b[g2w(cc, kwb + tig + 4)];
                mma16(d2[0][nt], af[0], bf);
                mma16(d2[1][nt], af[1], bf);
            }
        }
    }

    // ---- epilogue: x = x_mid + D2 + b2 ----
    const float* b2l = f2b + layer * W;
#pragma unroll
    for (int mt = 0; mt < 2; mt++) {
#pragma unroll
        for (int nt = 0; nt < 8; nt++) {
            int col = wn * 64 + nt * 8 + 2 * tig;
            int ra = wm * 32 + mt * 16 + g;
            float2 xm = *(const float2*)&g_x[xbase + (size_t)ra * W + col];
            float2 o;
            o.x = xm.x + d2[mt][nt][0] + b2l[col];
            o.y = xm.y + d2[mt][nt][1] + b2l[col + 1];
            *(float2*)&g_x[xbase + (size_t)ra * W + col] = o;
            int rb = ra + 8;
            float2 xm2 = *(const float2*)&g_x[xbase + (size_t)rb * W + col];
            o.x = xm2.x + d2[mt][nt][2] + b2l[col];
            o.y = xm2.y + d2[mt][nt][3] + b2l[col + 1];
            *(float2*)&g_x[xbase + (size_t)rb * W + col] = o;
        }
    }
}

// ---------------- K5: final projection ----------------
__global__ void __launch_bounds__(256) proj_kernel(
    const float* __restrict__ pw, const float* __restrict__ pb, float* __restrict__ out)
{
    __shared__ float xs[16][W];
    size_t t0 = (size_t)blockIdx.x * 16;
    for (int i = threadIdx.x; i < 16 * W; i += 256)
        xs[i >> 8][i & 255] = g_x[t0 * W + i];
    __syncthreads();
    if (threadIdx.x < 64) {
        int t = threadIdx.x >> 2, o = threadIdx.x & 3;
        float acc = pb[o];
#pragma unroll 8
        for (int c = 0; c < W; c++) acc += xs[t][c] * pw[c * CIN + o];
        out[(t0 + t) * CIN + o] = acc;
    }
}

// ---------------- launch ----------------
extern "C" void kernel_launch(void* const* d_in, const int* in_sizes, int n_in,
                              void* d_out, int out_size)
{
    const float* feat = (const float*)d_in[0];
    const float* coords = (const float*)d_in[1];
    const float* tn   = (const float*)d_in[2];
    const float* ew   = (const float*)d_in[3];
    const float* eb   = (const float*)d_in[4];
    const float* ln1g = (const float*)d_in[5];
    const float* ln1b = (const float*)d_in[6];
    const float* sw   = (const float*)d_in[7];
    const float* sb   = (const float*)d_in[8];
    const float* qkvw = (const float*)d_in[9];
    const float* qkvb = (const float*)d_in[10];
    const float* outw = (const float*)d_in[11];
    const float* outb = (const float*)d_in[12];
    const float* ln2g = (const float*)d_in[13];
    const float* ln2b = (const float*)d_in[14];
    const float* f1w  = (const float*)d_in[15];
    const float* f1b  = (const float*)d_in[16];
    const float* f2w  = (const float*)d_in[17];
    const float* f2b  = (const float*)d_in[18];
    const float* pw   = (const float*)d_in[19];
    const float* pb   = (const float*)d_in[20];

    static int attr_set = 0;
    if (!attr_set) {
        cudaFuncSetAttribute(ffn_mma_kernel, cudaFuncAttributeMaxDynamicSharedMemorySize, SM_FFN_BYTES);
        attr_set = 1;
    }

    embed_kernel<<<B * N / 16, 256>>>(feat, coords, tn, ew, eb);
    w1t_kernel<<<L * FF * W / 256, 256>>>(f1w);
    w2t_zero_kernel<<<NB_W2T + NB_Z + 1, 256>>>(f2w);

    for (int l = 0; l < L; l++) {
        slice_kernel<<<B * (N / TOK1), 256>>>(ln1g, ln1b, sw, sb, l);
        qkv_kernel<<<B * M, 768>>>(qkvw, qkvb, l);
        attn_kernel<<<B * H, 256>>>();
        zp_kernel<<<B * M, 256>>>(outw, outb, l);
        ffn_mma_kernel<<<B * (N / TOKF), 512, SM_FFN_BYTES>>>(ln2g, ln2b, f1b, f2b, l);
    }

    proj_kernel<<<(B * N) / 16, 256>>>(pw, pb, (float*)d_out);
}

// round 14
// speedup vs baseline: 1.0916x; 1.0095x over previous
#include <cuda_runtime.h>
#include <cuda_fp16.h>
#include <math.h>
#include <stdint.h>

#define B    4
#define N    16384
#define CIN  4
#define SD   3
#define W    256
#define L    8
#define M    32
#define H    8
#define FF   1024
#define TF   4
#define DH   32
#define TOK1 64
#define TOKF 128
#define JC2  128

__device__ float g_x[(size_t)B * N * W];
__device__ float g_w[(size_t)B * N * M];
__device__ float g_z[(size_t)L * B * M * W];
__device__ float g_wsum[L * B * M];
__device__ float g_qkv[B * M * 3 * W];
__device__ float g_o[B * M * W];
__device__ float g_zp[B * M * W];
__device__ __align__(16) __half g_w1t[(size_t)L * FF * W];   // [L][FF][W] fp16
__device__ __align__(16) __half g_w2t[(size_t)L * W * FF];   // [L][W][FF] fp16

// ---------- helpers ----------
__device__ __forceinline__ int hw2(int r, int wc) { return r * 128 + (wc ^ ((r & 7) << 2)); }
__device__ __forceinline__ int g2w(int r, int wc) { return r * 64  + (wc ^ ((r & 7) << 2)); }
__device__ __forceinline__ void mma16(float* d, const uint32_t* a, const uint32_t* b) {
    asm volatile("mma.sync.aligned.m16n8k16.row.col.f32.f16.f16.f32 "
        "{%0,%1,%2,%3}, {%4,%5,%6,%7}, {%8,%9}, {%0,%1,%2,%3};"
        : "+f"(d[0]), "+f"(d[1]), "+f"(d[2]), "+f"(d[3])
        : "r"(a[0]), "r"(a[1]), "r"(a[2]), "r"(a[3]), "r"(b[0]), "r"(b[1]));
}

// ---------------- K0: embed (16 tokens / block) ----------------
__global__ void __launch_bounds__(256) embed_kernel(
    const float* __restrict__ feat, const float* __restrict__ coords,
    const float* __restrict__ tn, const float* __restrict__ ew, const float* __restrict__ eb)
{
    __shared__ float f[16][16];
    int t0 = blockIdx.x * 16;
    int tid = threadIdx.x;
    {
        int t = tid >> 4, k = tid & 15;
        int token = t0 + t, b = token / N;
        float v = 0.f;
        if (k < CIN) v = feat[(size_t)token * CIN + k];
        else if (k < CIN + SD) v = coords[(size_t)token * SD + (k - CIN)];
        else if (k < 15) {
            int kk = k - 7, i = kk & 3;
            float ang = powf(1000.0f, -(float)i / (float)TF) * (tn[b] * 1000.0f);
            v = (kk < TF) ? sinf(ang) : cosf(ang);
        }
        f[t][k] = v;
    }
    __syncthreads();
    int c = tid;
    float wreg[15];
#pragma unroll
    for (int k = 0; k < 15; k++) wreg[k] = ew[k * W + c];
    float bias = eb[c];
#pragma unroll 4
    for (int t = 0; t < 16; t++) {
        float acc = bias;
#pragma unroll
        for (int k = 0; k < 15; k++) acc += f[t][k] * wreg[k];
        g_x[(size_t)(t0 + t) * W + c] = acc;
    }
}

// ---------------- weight transform + zero (fused) ----------------
__global__ void __launch_bounds__(256) w1t_kernel(const float* __restrict__ f1w)
{
    int idx = blockIdx.x * 256 + threadIdx.x;
    int l = idx / (FF * W), r = idx % (FF * W), j = r / W, c = r % W;
    g_w1t[((size_t)l * FF + j) * W + c] =
        __float2half(f1w[((size_t)l * W + c) * FF + j]);
}
#define NB_W2T (L * W * FF / 256)
#define NB_Z   (L * B * M * W / 256)
__global__ void __launch_bounds__(256) w2t_zero_kernel(const float* __restrict__ f2w)
{
    int bid = blockIdx.x;
    if (bid < NB_W2T) {
        int idx = bid * 256 + threadIdx.x;
        int l = idx / (W * FF), r = idx % (W * FF), c = r / FF, j = r % FF;
        g_w2t[((size_t)l * W + c) * FF + j] =
            __float2half(f2w[((size_t)l * FF + j) * W + c]);
    } else if (bid < NB_W2T + NB_Z) {
        int idx = (bid - NB_W2T) * 256 + threadIdx.x;
        g_z[idx] = 0.f;
    } else {
        for (int i = threadIdx.x; i < L * B * M; i += 256) g_wsum[i] = 0.f;
    }
}

// ---------------- K1: slice (64 tokens / block, dynamic smem) ----------------
// smem floats: hs[64][256]=16384, ws[64][32]=2048, inv[64]
#define SLICE_SMEM ((TOK1 * W + TOK1 * M + TOK1) * 4)

__global__ void __launch_bounds__(256, 3) slice_kernel(
    const float* __restrict__ ln_g, const float* __restrict__ ln_b,
    const float* __restrict__ sw, const float* __restrict__ sb, int layer)
{
    extern __shared__ float ssm[];
    float* hs  = ssm;                        // [64][256]
    float* ws  = ssm + TOK1 * W;             // [64][32]
    float* inv = ws + TOK1 * M;              // [64]
    int nb = N / TOK1, b = blockIdx.x / nb, t0 = (blockIdx.x % nb) * TOK1;
    int tid = threadIdx.x, warp = tid >> 5, lane = tid & 31;
    const float* g = ln_g + layer * W;
    const float* be = ln_b + layer * W;
    float* zdst = g_z + (size_t)layer * B * M * W;
    float* wsdst = g_wsum + layer * B * M;

    // LN: 8 warps x 8 tokens
    for (int t = warp; t < TOK1; t += 8) {
        const float* xr = g_x + ((size_t)(b * N + t0 + t)) * W;
        float v[8]; float s = 0.f, s2 = 0.f;
#pragma unroll
        for (int i = 0; i < 8; i++) { v[i] = xr[lane + 32 * i]; s += v[i]; s2 += v[i] * v[i]; }
#pragma unroll
        for (int o = 16; o > 0; o >>= 1) {
            s += __shfl_xor_sync(0xffffffffu, s, o);
            s2 += __shfl_xor_sync(0xffffffffu, s2, o);
        }
        float mean = s * (1.0f / W), var = s2 * (1.0f / W) - mean * mean;
        float r = rsqrtf(var + 1e-5f);
#pragma unroll
        for (int i = 0; i < 8; i++) {
            int c = lane + 32 * i;
            hs[t * W + c] = (v[i] - mean) * r * g[c] + be[c];
        }
    }
    __syncthreads();

    // logits: 2 rounds of (t, 4 m's) per thread
    const float* swl = sw + (size_t)layer * W * M;
#pragma unroll
    for (int r = 0; r < 2; r++) {
        int idx = tid + 256 * r;
        int t = idx >> 3, m4 = (idx & 7) << 2;
        float4 acc = *(const float4*)&sb[layer * M + m4];
#pragma unroll 4
        for (int c4 = 0; c4 < W; c4 += 4) {
            float4 hv = *(const float4*)&hs[t * W + c4];
            float4 s0 = *(const float4*)&swl[(c4 + 0) * M + m4];
            float4 s1 = *(const float4*)&swl[(c4 + 1) * M + m4];
            float4 s2 = *(const float4*)&swl[(c4 + 2) * M + m4];
            float4 s3 = *(const float4*)&swl[(c4 + 3) * M + m4];
            acc.x += hv.x * s0.x + hv.y * s1.x + hv.z * s2.x + hv.w * s3.x;
            acc.y += hv.x * s0.y + hv.y * s1.y + hv.z * s2.y + hv.w * s3.y;
            acc.z += hv.x * s0.z + hv.y * s1.z + hv.z * s2.z + hv.w * s3.z;
            acc.w += hv.x * s0.w + hv.y * s1.w + hv.z * s2.w + hv.w * s3.w;
        }
        *(float4*)&ws[t * M + m4] = acc;
    }
    __syncthreads();

    // softmax over M per token
    if (tid < TOK1) {
        float mx = -1e30f;
#pragma unroll
        for (int m = 0; m < M; m++) mx = fmaxf(mx, ws[tid * M + m]);
        float sum = 0.f;
#pragma unroll
        for (int m = 0; m < M; m++) { float e = expf(ws[tid * M + m] - mx); ws[tid * M + m] = e; sum += e; }
        inv[tid] = 1.0f / sum;
    }
    __syncthreads();

    // normalize + write w
#pragma unroll
    for (int r = 0; r < 2; r++) {
        int idx = tid + 256 * r;
        int t = idx >> 3, m4 = (idx & 7) << 2;
        float iv = inv[t];
        float4 v = *(const float4*)&ws[t * M + m4];
        v.x *= iv; v.y *= iv; v.z *= iv; v.w *= iv;
        *(float4*)&ws[t * M + m4] = v;
        *(float4*)&g_w[((size_t)(b * N + t0 + t)) * M + m4] = v;
    }
    __syncthreads();

    if (tid < M) {
        float s = 0.f;
#pragma unroll
        for (int t = 0; t < TOK1; t++) s += ws[t * M + tid];
        atomicAdd(&wsdst[b * M + tid], s);
    }

    // z accumulation: thread owns channel c = tid
    float zacc[M];
#pragma unroll
    for (int m = 0; m < M; m++) zacc[m] = 0.f;
    for (int t = 0; t < TOK1; t++) {
        float hv = hs[t * W + tid];
#pragma unroll
        for (int mq = 0; mq < 8; mq++) {
            float4 wv = *(const float4*)&ws[t * M + (mq << 2)];
            zacc[(mq << 2) + 0] += wv.x * hv;
            zacc[(mq << 2) + 1] += wv.y * hv;
            zacc[(mq << 2) + 2] += wv.z * hv;
            zacc[(mq << 2) + 3] += wv.w * hv;
        }
    }
#pragma unroll
    for (int m = 0; m < M; m++) atomicAdd(&zdst[(b * M + m) * W + tid], zacc[m]);
}

// ---------------- K2a: qkv (768 threads) ----------------
__global__ void __launch_bounds__(768) qkv_kernel(
    const float* __restrict__ qkvw, const float* __restrict__ qkvb, int layer)
{
    int b = blockIdx.x / M, m = blockIdx.x % M;
    __shared__ float zs[W];
    int tid = threadIdx.x;
    if (tid < W) {
        float wsv = fmaxf(g_wsum[layer * B * M + b * M + m], 1e-8f);
        zs[tid] = g_z[(size_t)layer * B * M * W + (size_t)(b * M + m) * W + tid] / wsv;
    }
    __syncthreads();
    const float* wq = qkvw + (size_t)layer * W * 3 * W;
    float acc = qkvb[layer * 3 * W + tid];
#pragma unroll 8
    for (int c = 0; c < W; c++) acc += zs[c] * wq[(size_t)c * (3 * W) + tid];
    g_qkv[(size_t)(b * M + m) * (3 * W) + tid] = acc;
}

__global__ void __launch_bounds__(256) attn_kernel()
{
    int b = blockIdx.x / H, h = blockIdx.x % H;
    __shared__ float q[M][DH], k[M][DH], v[M][DH], a[M][M];
    int tid = threadIdx.x;
    for (int i = tid; i < M * DH; i += 256) {
        int m = i / DH, d = i % DH;
        const float* base = g_qkv + (size_t)(b * M + m) * (3 * W);
        q[m][d] = base[h * DH + d];
        k[m][d] = base[W + h * DH + d];
        v[m][d] = base[2 * W + h * DH + d];
    }
    __syncthreads();
    const float scale = 0.17677669529663687f;
    for (int i = tid; i < M * M; i += 256) {
        int m = i / M, n2 = i % M;
        float acc = 0.f;
#pragma unroll
        for (int d = 0; d < DH; d++) acc += q[m][d] * k[n2][d];
        a[m][n2] = acc * scale;
    }
    __syncthreads();
    if (tid < M) {
        float mx = -1e30f;
#pragma unroll
        for (int n2 = 0; n2 < M; n2++) mx = fmaxf(mx, a[tid][n2]);
        float s = 0.f;
#pragma unroll
        for (int n2 = 0; n2 < M; n2++) { float e = expf(a[tid][n2] - mx); a[tid][n2] = e; s += e; }
        float is = 1.0f / s;
#pragma unroll
        for (int n2 = 0; n2 < M; n2++) a[tid][n2] *= is;
    }
    __syncthreads();
    for (int i = tid; i < M * DH; i += 256) {
        int m = i / DH, d = i % DH;
        float acc = 0.f;
#pragma unroll
        for (int n2 = 0; n2 < M; n2++) acc += a[m][n2] * v[n2][d];
        g_o[(size_t)(b * M + m) * W + h * DH + d] = acc;
    }
}
__global__ void __launch_bounds__(256) zp_kernel(
    const float* __restrict__ ow, const float* __restrict__ ob, int layer)
{
    int b = blockIdx.x / M, m = blockIdx.x % M;
    __shared__ float os[W];
    os[threadIdx.x] = g_o[(size_t)(b * M + m) * W + threadIdx.x];
    __syncthreads();
    const float* wl = ow + (size_t)layer * W * W;
    float acc = ob[layer * W + threadIdx.x];
#pragma unroll 8
    for (int k2 = 0; k2 < W; k2++) acc += os[k2] * wl[(size_t)k2 * W + threadIdx.x];
    g_zp[(size_t)(b * M + m) * W + threadIdx.x] = acc;
}

// ---------------- K3: FFN fp16 m16n8k16, JC2=128 (8 chunks) ----------------
#define WO_G 16384
#define WO_B 24576
#define SM_FFN_BYTES (40960 * 4)

__global__ void __launch_bounds__(512, 1) ffn_mma_kernel(
    const float* __restrict__ ln2g, const float* __restrict__ ln2b,
    const float* __restrict__ f1b, const float* __restrict__ f2b, int layer)
{
    extern __shared__ uint32_t usm[];
    uint32_t* u_h2 = usm;
    uint32_t* u_g  = usm + WO_G;
    uint32_t* u_b  = usm + WO_B;
    __half* h_h2 = (__half*)u_h2;
    int tid = threadIdx.x;
    int warp = tid >> 5, lane = tid & 31, g = lane >> 2, tig = lane & 3;
    int nb = N / TOKF, b = blockIdx.x / nb, t0 = (blockIdx.x % nb) * TOKF;
    size_t xbase = ((size_t)(b * N) + t0) * W;

    int c = tid & 255, half_ = tid >> 8;
    float zpc[M];
#pragma unroll
    for (int m = 0; m < M; m++) zpc[m] = g_zp[(size_t)(b * M + m) * W + c];
    {
        float* s_w = (float*)u_g;
        for (int i = tid; i < TOKF * M; i += 512)
            s_w[i] = g_w[((size_t)(b * N) + t0 + i / M) * M + (i % M)];
        __syncthreads();
        int wcol = c >> 1, hi = c & 1;
        for (int t = half_ * 64; t < half_ * 64 + 64; t++) {
            float acc = g_x[xbase + (size_t)t * W + c];
#pragma unroll
            for (int m = 0; m < M; m++) acc += s_w[t * M + m] * zpc[m];
            g_x[xbase + (size_t)t * W + c] = acc;
            h_h2[(t * 128 + (wcol ^ ((t & 7) << 2))) * 2 + hi] = __float2half(acc);
        }
    }
    __syncthreads();

    {
        const float* g2 = ln2g + layer * W;
        const float* b2 = ln2b + layer * W;
        for (int rr = 0; rr < 8; rr++) {
            int r = warp * 8 + rr;
            if (r >= TOKF) break;
            float v[8]; float s = 0.f, s2 = 0.f;
#pragma unroll
            for (int i = 0; i < 8; i++) {
                int ci = lane + 32 * i;
                v[i] = __half2float(h_h2[(r * 128 + ((ci >> 1) ^ ((r & 7) << 2))) * 2 + (ci & 1)]);
                s += v[i]; s2 += v[i] * v[i];
            }
#pragma unroll
            for (int o = 16; o > 0; o >>= 1) {
                s += __shfl_xor_sync(0xffffffffu, s, o);
                s2 += __shfl_xor_sync(0xffffffffu, s2, o);
            }
            float mean = s * (1.0f / W), var = s2 * (1.0f / W) - mean * mean;
            float rs = rsqrtf(var + 1e-5f);
#pragma unroll
            for (int i = 0; i < 8; i++) {
                int ci = lane + 32 * i;
                h_h2[(r * 128 + ((ci >> 1) ^ ((r & 7) << 2))) * 2 + (ci & 1)] =
                    __float2half((v[i] - mean) * rs * g2[ci] + b2[ci]);
            }
        }
    }

    const __half* w1l = g_w1t + (size_t)layer * FF * W;
    const __half* w2l = g_w2t + (size_t)layer * W * FF;
    const float* b1l = f1b + layer * FF;

    int wm = warp >> 2, wn = warp & 3;
    float d2[2][8][4];
#pragma unroll
    for (int mt = 0; mt < 2; mt++)
#pragma unroll
        for (int nt = 0; nt < 8; nt++)
#pragma unroll
            for (int q = 0; q < 4; q++) d2[mt][nt][q] = 0.f;

    for (int chunk = 0; chunk < 8; chunk++) {
        int j0 = chunk * JC2;

        __syncthreads();
#pragma unroll
        for (int it = 0; it < 8; it++) {
            int idx = it * 512 + tid;
            int jl = idx >> 5, wc4 = (idx & 31) << 2;
            uint4 v = *(const uint4*)&w1l[(size_t)(j0 + jl) * W + wc4 * 2];
            *(uint4*)&u_b[jl * 128 + (wc4 ^ ((jl & 7) << 2))] = v;
        }
        __syncthreads();

        float d1[2][4][4];
#pragma unroll
        for (int mt = 0; mt < 2; mt++)
#pragma unroll
            for (int nt = 0; nt < 4; nt++)
#pragma unroll
                for (int q = 0; q < 4; q++) d1[mt][nt][q] = 0.f;

#pragma unroll 4
        for (int ks = 0; ks < 16; ks++) {
            int kwb = ks * 8;
            uint32_t af[2][4];
#pragma unroll
            for (int mt = 0; mt < 2; mt++) {
                int r0 = wm * 32 + mt * 16 + g;
                af[mt][0] = u_h2[hw2(r0,     kwb + tig)];
                af[mt][1] = u_h2[hw2(r0 + 8, kwb + tig)];
                af[mt][2] = u_h2[hw2(r0,     kwb + tig + 4)];
                af[mt][3] = u_h2[hw2(r0 + 8, kwb + tig + 4)];
            }
#pragma unroll
            for (int nt = 0; nt < 4; nt++) {
                int jl = wn * 32 + nt * 8 + g;
                uint32_t bf[2];
                bf[0] = u_b[hw2(jl, kwb + tig)];
                bf[1] = u_b[hw2(jl, kwb + tig + 4)];
                mma16(d1[0][nt], af[0], bf);
                mma16(d1[1][nt], af[1], bf);
            }
        }
        __syncthreads();

#pragma unroll
        for (int mt = 0; mt < 2; mt++) {
#pragma unroll
            for (int nt = 0; nt < 4; nt++) {
                int r0 = wm * 32 + mt * 16 + g;
                int jc = wn * 32 + nt * 8 + 2 * tig;
                int wc = wn * 16 + nt * 4 + tig;
                float x0 = d1[mt][nt][0] + b1l[j0 + jc];
                float x1 = d1[mt][nt][1] + b1l[j0 + jc + 1];
                float x2 = d1[mt][nt][2] + b1l[j0 + jc];
                float x3 = d1[mt][nt][3] + b1l[j0 + jc + 1];
                float g0 = 0.5f * x0 * (1.0f + erff(x0 * 0.7071067811865476f));
                float g1 = 0.5f * x1 * (1.0f + erff(x1 * 0.7071067811865476f));
                float g2v = 0.5f * x2 * (1.0f + erff(x2 * 0.7071067811865476f));
                float g3 = 0.5f * x3 * (1.0f + erff(x3 * 0.7071067811865476f));
                __half2 p0 = __floats2half2_rn(g0, g1);
                __half2 p1 = __floats2half2_rn(g2v, g3);
                u_g[g2w(r0,     wc)] = *(uint32_t*)&p0;
                u_g[g2w(r0 + 8, wc)] = *(uint32_t*)&p1;
            }
        }
#pragma unroll
        for (int it = 0; it < 8; it++) {
            int idx = it * 512 + tid;
            int cc = idx >> 4, wc4 = (idx & 15) << 2;
            uint4 v = *(const uint4*)&w2l[(size_t)cc * FF + j0 + wc4 * 2];
            *(uint4*)&u_b[cc * 64 + (wc4 ^ ((cc & 7) << 2))] = v;
        }
        __syncthreads();

#pragma unroll 2
        for (int ks = 0; ks < 8; ks++) {
            int kwb = ks * 8;
            uint32_t af[2][4];
#pragma unroll
            for (int mt = 0; mt < 2; mt++) {
                int r0 = wm * 32 + mt * 16 + g;
                af[mt][0] = u_g[g2w(r0,     kwb + tig)];
                af[mt][1] = u_g[g2w(r0 + 8, kwb + tig)];
                af[mt][2] = u_g[g2w(r0,     kwb + tig + 4)];
                af[mt][3] = u_g[g2w(r0 + 8, kwb + tig + 4)];
            }
#pragma unroll
            for (int nt = 0; nt < 8; nt++) {
                int cc = wn * 64 + nt * 8 + g;
                uint32_t bf[2];
                bf[0] = u_b[g2w(cc, kwb + tig)];
                bf[1] = u_b[g2w(cc, kwb + tig + 4)];
                mma16(d2[0][nt], af[0], bf);
                mma16(d2[1][nt], af[1], bf);
            }
        }
    }

    const float* b2l = f2b + layer * W;
#pragma unroll
    for (int mt = 0; mt < 2; mt++) {
#pragma unroll
        for (int nt = 0; nt < 8; nt++) {
            int col = wn * 64 + nt * 8 + 2 * tig;
            int ra = wm * 32 + mt * 16 + g;
            float2 xm = *(const float2*)&g_x[xbase + (size_t)ra * W + col];
            float2 o;
            o.x = xm.x + d2[mt][nt][0] + b2l[col];
            o.y = xm.y + d2[mt][nt][1] + b2l[col + 1];
            *(float2*)&g_x[xbase + (size_t)ra * W + col] = o;
            int rb = ra + 8;
            float2 xm2 = *(const float2*)&g_x[xbase + (size_t)rb * W + col];
            o.x = xm2.x + d2[mt][nt][2] + b2l[col];
            o.y = xm2.y + d2[mt][nt][3] + b2l[col + 1];
            *(float2*)&g_x[xbase + (size_t)rb * W + col] = o;
        }
    }
}

// ---------------- K5: final projection ----------------
__global__ void __launch_bounds__(256) proj_kernel(
    const float* __restrict__ pw, const float* __restrict__ pb, float* __restrict__ out)
{
    __shared__ float xs[16][W];
    size_t t0 = (size_t)blockIdx.x * 16;
    for (int i = threadIdx.x; i < 16 * W; i += 256)
        xs[i >> 8][i & 255] = g_x[t0 * W + i];
    __syncthreads();
    if (threadIdx.x < 64) {
        int t = threadIdx.x >> 2, o = threadIdx.x & 3;
        float acc = pb[o];
#pragma unroll 8
        for (int c = 0; c < W; c++) acc += xs[t][c] * pw[c * CIN + o];
        out[(t0 + t) * CIN + o] = acc;
    }
}

// ---------------- launch ----------------
extern "C" void kernel_launch(void* const* d_in, const int* in_sizes, int n_in,
                              void* d_out, int out_size)
{
    const float* feat = (const float*)d_in[0];
    const float* coords = (const float*)d_in[1];
    const float* tn   = (const float*)d_in[2];
    const float* ew   = (const float*)d_in[3];
    const float* eb   = (const float*)d_in[4];
    const float* ln1g = (const float*)d_in[5];
    const float* ln1b = (const float*)d_in[6];
    const float* sw   = (const float*)d_in[7];
    const float* sb   = (const float*)d_in[8];
    const float* qkvw = (const float*)d_in[9];
    const float* qkvb = (const float*)d_in[10];
    const float* outw = (const float*)d_in[11];
    const float* outb = (const float*)d_in[12];
    const float* ln2g = (const float*)d_in[13];
    const float* ln2b = (const float*)d_in[14];
    const float* f1w  = (const float*)d_in[15];
    const float* f1b  = (const float*)d_in[16];
    const float* f2w  = (const float*)d_in[17];
    const float* f2b  = (const float*)d_in[18];
    const float* pw   = (const float*)d_in[19];
    const float* pb   = (const float*)d_in[20];

    static int attr_set = 0;
    if (!attr_set) {
        cudaFuncSetAttribute(ffn_mma_kernel, cudaFuncAttributeMaxDynamicSharedMemorySize, SM_FFN_BYTES);
        cudaFuncSetAttribute(slice_kernel, cudaFuncAttributeMaxDynamicSharedMemorySize, SLICE_SMEM);
        attr_set = 1;
    }

    embed_kernel<<<B * N / 16, 256>>>(feat, coords, tn, ew, eb);
    w1t_kernel<<<L * FF * W / 256, 256>>>(f1w);
    w2t_zero_kernel<<<NB_W2T + NB_Z + 1, 256>>>(f2w);

    for (int l = 0; l < L; l++) {
        slice_kernel<<<B * (N / TOK1), 256, SLICE_SMEM>>>(ln1g, ln1b, sw, sb, l);
        qkv_kernel<<<B * M, 768>>>(qkvw, qkvb, l);
        attn_kernel<<<B * H, 256>>>();
        zp_kernel<<<B * M, 256>>>(outw, outb, l);
        ffn_mma_kernel<<<B * (N / TOKF), 512, SM_FFN_BYTES>>>(ln2g, ln2b, f1b, f2b, l);
    }

    proj_kernel<<<(B * N) / 16, 256>>>(pw, pb, (float*)d_out);
}